// round 6
// baseline (speedup 1.0000x reference)
#include <cuda_runtime.h>
#include <cuda_bf16.h>
#include <math.h>
#include <stdint.h>

// ---------------------------------------------------------------------------
// Problem constants (B=8, T=4096, D=H=768)
// ---------------------------------------------------------------------------
#define Bn   8
#define Tn   4096
#define Dn   768
#define Hn   768
#define Mn   (Bn * Tn)      // 32768
#define BHn  (Bn * Hn)      // 6144 scan lanes
#define NCH  64
#define TC   (Tn / NCH)     // 64

// GEMM tiling
#define TM   128            // CTA M tile
#define TN   64             // CTA N tile
#define BK   32             // K chunk per stage
#define NKI  (Dn / BK)      // 24 iterations

// Padded smem row: 32 halves data + 8 pad = 40 halves = 80 bytes.
// 8-row ldmatrix phases at stride 80B hit banks (r*20)%32 -> all distinct.
#define ROWB 80
#define A_TILE_B   (TM * ROWB)           // 10240
#define B_TILE_B   (TN * ROWB)           // 5120
#define STG_B      (2 * A_TILE_B + 6 * B_TILE_B)   // 51200
#define SMEM_TOTAL (2 * STG_B)                     // 102400

// ---------------------------------------------------------------------------
// Device scratch
// ---------------------------------------------------------------------------
__device__ float g_a [(size_t)Mn * Hn];
__device__ float g_bv[(size_t)Mn * Hn];
__device__ float g_cA [NCH * BHn];
__device__ float g_cB [NCH * BHn];
__device__ float g_hin[NCH * BHn];

__device__ __nv_bfloat16 g_xhi[(size_t)Mn * Dn];
__device__ __nv_bfloat16 g_xlo[(size_t)Mn * Dn];
__device__ __nv_bfloat16 g_fwhi[Hn * Dn];
__device__ __nv_bfloat16 g_fwlo[Hn * Dn];
__device__ __nv_bfloat16 g_iwhi[Hn * Dn];
__device__ __nv_bfloat16 g_iwlo[Hn * Dn];
__device__ __nv_bfloat16 g_hwhi[Hn * Dn];
__device__ __nv_bfloat16 g_hwlo[Hn * Dn];

// ---------------------------------------------------------------------------
// Helpers
// ---------------------------------------------------------------------------
__device__ __forceinline__ uint32_t smem_u32(const void* p) {
    uint32_t a;
    asm("{ .reg .u64 t; cvta.to.shared.u64 t, %1; cvt.u32.u64 %0, t; }" : "=r"(a) : "l"(p));
    return a;
}
__device__ __forceinline__ void cpa16(uint32_t dst, const void* src) {
    asm volatile("cp.async.cg.shared.global [%0], [%1], 16;" :: "r"(dst), "l"(src) : "memory");
}
#define CPA_COMMIT() asm volatile("cp.async.commit_group;" ::: "memory")
#define CPA_WAIT1()  asm volatile("cp.async.wait_group 1;" ::: "memory")
#define CPA_WAIT0()  asm volatile("cp.async.wait_group 0;" ::: "memory")

// ldmatrix x4: 4 8x8 b16 tiles; lane supplies one row address per tile group.
__device__ __forceinline__ void ldm4(uint32_t& r0, uint32_t& r1,
                                     uint32_t& r2, uint32_t& r3, uint32_t a) {
    asm volatile("ldmatrix.sync.aligned.m8n8.x4.shared.b16 {%0,%1,%2,%3}, [%4];"
                 : "=r"(r0), "=r"(r1), "=r"(r2), "=r"(r3) : "r"(a));
}

// mma.sync m16n8k16 bf16 * bf16 -> f32, row.col (both operands K-contiguous)
__device__ __forceinline__ void mma16816(float* c, const uint32_t* a, const uint32_t* b) {
    asm volatile(
        "mma.sync.aligned.m16n8k16.row.col.f32.bf16.bf16.f32 "
        "{%0,%1,%2,%3}, {%4,%5,%6,%7}, {%8,%9}, {%0,%1,%2,%3};"
        : "+f"(c[0]), "+f"(c[1]), "+f"(c[2]), "+f"(c[3])
        : "r"(a[0]), "r"(a[1]), "r"(a[2]), "r"(a[3]), "r"(b[0]), "r"(b[1]));
}

// ---------------------------------------------------------------------------
// Split-conversion: fp32 -> (bf16 hi, bf16 lo = bf16(v - hi))
// ---------------------------------------------------------------------------
__global__ void convert_split(const float* __restrict__ in,
                              __nv_bfloat16* __restrict__ hi,
                              __nv_bfloat16* __restrict__ lo, int n4) {
    int i = blockIdx.x * blockDim.x + threadIdx.x;
    if (i >= n4) return;
    float4 v = ((const float4*)in)[i];
    float f[4] = {v.x, v.y, v.z, v.w};
    __nv_bfloat162 h01, h23, l01, l23;
    __nv_bfloat16 h0 = __float2bfloat16(f[0]);
    __nv_bfloat16 h1 = __float2bfloat16(f[1]);
    __nv_bfloat16 h2 = __float2bfloat16(f[2]);
    __nv_bfloat16 h3 = __float2bfloat16(f[3]);
    h01.x = h0; h01.y = h1; h23.x = h2; h23.y = h3;
    l01.x = __float2bfloat16(f[0] - __bfloat162float(h0));
    l01.y = __float2bfloat16(f[1] - __bfloat162float(h1));
    l23.x = __float2bfloat16(f[2] - __bfloat162float(h2));
    l23.y = __float2bfloat16(f[3] - __bfloat162float(h3));
    ((__nv_bfloat162*)hi)[2 * i]     = h01;
    ((__nv_bfloat162*)hi)[2 * i + 1] = h23;
    ((__nv_bfloat162*)lo)[2 * i]     = l01;
    ((__nv_bfloat162*)lo)[2 * i + 1] = l23;
}

// ---------------------------------------------------------------------------
// Triple-GEMM via mma.sync bf16 split + ldmatrix fragment loads.
// Grid: x = H tiles (fast -> weights L2-hot), y = M tiles. Block 256 (8 warps).
// ---------------------------------------------------------------------------
__global__ __launch_bounds__(256, 1) void gemm_mma(
    const float* __restrict__ fb, const float* __restrict__ ib,
    const float* __restrict__ hb)
{
    extern __shared__ __align__(128) char smem[];
    const uint32_t sb = smem_u32(smem);
    const int tid = threadIdx.x;
    const int wid = tid >> 5;
    const int lid = tid & 31;
    const int g   = lid >> 2;      // groupID 0..7
    const int tig = lid & 3;       // thread-in-group
    const int wm  = wid & 3;       // warp M index (0..3) -> rows wm*32
    const int wn  = wid >> 2;      // warp N index (0..1) -> cols wn*32
    const int bn  = blockIdx.x * TN;
    const int bm  = blockIdx.y * TM;

    // ldmatrix lane->address offsets (within a 16-row x 16-col frag group)
    // A x4 tiles: (r0-7,k0-7),(r8-15,k0-7),(r0-7,k8-15),(r8-15,k8-15)
    const uint32_t aOff = (uint32_t)((lid & 15) * ROWB + (lid >> 4) * 16);
    // B x4 tiles: (n0-7,k0-7),(n0-7,k8-15),(n8-15,k0-7),(n8-15,k8-15)
    const uint32_t bOff = (uint32_t)(((lid >> 4) * 8 + (lid & 7)) * ROWB
                                     + ((lid >> 3) & 1) * 16);

    // ---- stage loader (cp.async) ----
    auto issue_stage = [&](int stage, int k0) {
        const uint32_t s = sb + stage * STG_B;
        #pragma unroll
        for (int rr = 0; rr < 2; rr++) {
            int i = tid + rr * 256;
            int row = i >> 2, c = i & 3;
            uint32_t dst = s + row * ROWB + c * 16;
            size_t gi = (size_t)(bm + row) * Dn + k0 + c * 8;
            cpa16(dst,            g_xhi + gi);
            cpa16(dst + A_TILE_B, g_xlo + gi);
        }
        {
            int row = tid >> 2, c = tid & 3;
            uint32_t dstb = s + 2 * A_TILE_B + row * ROWB + c * 16;
            size_t gi = (size_t)(bn + row) * Dn + k0 + c * 8;
            cpa16(dstb + 0 * B_TILE_B, g_fwhi + gi);
            cpa16(dstb + 1 * B_TILE_B, g_fwlo + gi);
            cpa16(dstb + 2 * B_TILE_B, g_iwhi + gi);
            cpa16(dstb + 3 * B_TILE_B, g_iwlo + gi);
            cpa16(dstb + 4 * B_TILE_B, g_hwhi + gi);
            cpa16(dstb + 5 * B_TILE_B, g_hwlo + gi);
        }
    };

    float acc[3][2][4][4];
    #pragma unroll
    for (int p = 0; p < 3; p++)
        #pragma unroll
        for (int mi = 0; mi < 2; mi++)
            #pragma unroll
            for (int ni = 0; ni < 4; ni++)
                #pragma unroll
                for (int q = 0; q < 4; q++) acc[p][mi][ni][q] = 0.0f;

    issue_stage(0, 0);  CPA_COMMIT();
    issue_stage(1, BK); CPA_COMMIT();

    for (int k = 0; k < NKI; k++) {
        if (k < NKI - 2) CPA_WAIT1(); else CPA_WAIT0();
        __syncthreads();

        const uint32_t s = sb + (k & 1) * STG_B;
        #pragma unroll
        for (int ks = 0; ks < 2; ks++) {          // two k16 steps in BK=32
            const uint32_t kOff = ks * 32;        // 16 halves = 32 bytes

            // A fragments via ldmatrix.x4: hi & lo, 2 m-tiles
            uint32_t ah[2][4], al[2][4];
            const uint32_t aBase = s + (wm * 32) * ROWB + kOff + aOff;
            ldm4(ah[0][0], ah[0][1], ah[0][2], ah[0][3], aBase);
            ldm4(ah[1][0], ah[1][1], ah[1][2], ah[1][3], aBase + 16 * ROWB);
            ldm4(al[0][0], al[0][1], al[0][2], al[0][3], aBase + A_TILE_B);
            ldm4(al[1][0], al[1][1], al[1][2], al[1][3], aBase + A_TILE_B + 16 * ROWB);

            const uint32_t bBase = s + 2 * A_TILE_B + (wn * 32) * ROWB + kOff + bOff;
            #pragma unroll
            for (int p = 0; p < 3; p++) {
                uint32_t bh[4][2], bl[4][2];
                const uint32_t ph = bBase + (2 * p) * B_TILE_B;
                ldm4(bh[0][0], bh[0][1], bh[1][0], bh[1][1], ph);
                ldm4(bh[2][0], bh[2][1], bh[3][0], bh[3][1], ph + 16 * ROWB);
                ldm4(bl[0][0], bl[0][1], bl[1][0], bl[1][1], ph + B_TILE_B);
                ldm4(bl[2][0], bl[2][1], bl[3][0], bl[3][1], ph + B_TILE_B + 16 * ROWB);
                #pragma unroll
                for (int mi = 0; mi < 2; mi++)
                    #pragma unroll
                    for (int ni = 0; ni < 4; ni++) {
                        mma16816(acc[p][mi][ni], ah[mi], bh[ni]);  // hi*hi
                        mma16816(acc[p][mi][ni], ah[mi], bl[ni]);  // hi*lo
                        mma16816(acc[p][mi][ni], al[mi], bh[ni]);  // lo*hi
                    }
            }
        }
        __syncthreads();
        if (k + 2 < NKI) { issue_stage(k & 1, (k + 2) * BK); CPA_COMMIT(); }
    }

    // ---- epilogue: sigmoid gating -> g_a / g_bv ----
    #pragma unroll
    for (int ni = 0; ni < 4; ni++) {
        const int col = bn + wn * 32 + ni * 8 + tig * 2;
        const float fb0 = fb[col], fb1 = fb[col + 1];
        const float ib0 = ib[col], ib1 = ib[col + 1];
        const float hb0 = hb[col], hb1 = hb[col + 1];
        #pragma unroll
        for (int mi = 0; mi < 2; mi++) {
            #pragma unroll
            for (int half = 0; half < 2; half++) {
                const int m = bm + wm * 32 + mi * 16 + g + half * 8;
                const float F0 = acc[0][mi][ni][half * 2 + 0] + fb0;
                const float F1 = acc[0][mi][ni][half * 2 + 1] + fb1;
                const float I0 = acc[1][mi][ni][half * 2 + 0] + ib0;
                const float I1 = acc[1][mi][ni][half * 2 + 1] + ib1;
                const float H0 = acc[2][mi][ni][half * 2 + 0] + hb0;
                const float H1 = acc[2][mi][ni][half * 2 + 1] + hb1;
                const float f0 = 1.0f / (1.0f + expf(-F0));
                const float f1 = 1.0f / (1.0f + expf(-F1));
                const float i0 = 1.0f / (1.0f + expf(-I0));
                const float i1 = 1.0f / (1.0f + expf(-I1));
                const float v0 = 1.0f / (f0 + i0 + 1e-8f);
                const float v1 = 1.0f / (f1 + i1 + 1e-8f);
                float2 av = make_float2(f0 * v0, f1 * v1);
                float2 bv = make_float2(i0 * v0 * H0, i1 * v1 * H1);
                const size_t base = (size_t)m * Hn + col;
                *(float2*)&g_a [base] = av;
                *(float2*)&g_bv[base] = bv;
            }
        }
    }
}

// ---------------------------------------------------------------------------
// Scan (3-pass chunked), float4-vectorized over h.
// ---------------------------------------------------------------------------
__global__ __launch_bounds__(256) void scan_chunk()
{
    const int lane4 = blockIdx.x * blockDim.x + threadIdx.x;   // 0..BHn/4-1
    const int chunk = blockIdx.y;
    const int h4 = lane4 * 4;
    const int b = h4 / Hn;
    const int h = h4 - b * Hn;

    size_t idx = ((size_t)(b * Tn + chunk * TC)) * Hn + h;
    float4 A = make_float4(1.f, 1.f, 1.f, 1.f);
    float4 Bc = make_float4(0.f, 0.f, 0.f, 0.f);
    #pragma unroll 4
    for (int t = 0; t < TC; t++) {
        float4 a  = *(const float4*)&g_a [idx];
        float4 bb = *(const float4*)&g_bv[idx];
        Bc.x = fmaf(a.x, Bc.x, bb.x); A.x *= a.x;
        Bc.y = fmaf(a.y, Bc.y, bb.y); A.y *= a.y;
        Bc.z = fmaf(a.z, Bc.z, bb.z); A.z *= a.z;
        Bc.w = fmaf(a.w, Bc.w, bb.w); A.w *= a.w;
        idx += Hn;
    }
    *(float4*)&g_cA[chunk * BHn + h4] = A;
    *(float4*)&g_cB[chunk * BHn + h4] = Bc;
}

__global__ __launch_bounds__(256) void scan_carry(const float* __restrict__ h0)
{
    const int lane = blockIdx.x * blockDim.x + threadIdx.x;
    float h = h0[lane];
    #pragma unroll
    for (int c = 0; c < NCH; c++) {
        g_hin[c * BHn + lane] = h;
        h = fmaf(g_cA[c * BHn + lane], h, g_cB[c * BHn + lane]);
    }
}

__global__ __launch_bounds__(256) void scan_apply(float* __restrict__ out)
{
    const int lane4 = blockIdx.x * blockDim.x + threadIdx.x;
    const int chunk = blockIdx.y;
    const int h4 = lane4 * 4;
    const int b = h4 / Hn;
    const int h = h4 - b * Hn;

    float4 hc = *(const float4*)&g_hin[chunk * BHn + h4];
    size_t idx = ((size_t)(b * Tn + chunk * TC)) * Hn + h;
    #pragma unroll 4
    for (int t = 0; t < TC; t++) {
        float4 a  = *(const float4*)&g_a [idx];
        float4 bb = *(const float4*)&g_bv[idx];
        hc.x = fmaf(a.x, hc.x, bb.x);
        hc.y = fmaf(a.y, hc.y, bb.y);
        hc.z = fmaf(a.z, hc.z, bb.z);
        hc.w = fmaf(a.w, hc.w, bb.w);
        *(float4*)&out[idx] = hc;
        idx += Hn;
    }
}

// ---------------------------------------------------------------------------
// Launch
// ---------------------------------------------------------------------------
extern "C" void kernel_launch(void* const* d_in, const int* in_sizes, int n_in,
                              void* d_out, int out_size)
{
    const float* x  = (const float*)d_in[0];
    const float* h0 = (const float*)d_in[1];
    const float* fw = (const float*)d_in[2];
    const float* fb = (const float*)d_in[3];
    const float* iw = (const float*)d_in[4];
    const float* ib = (const float*)d_in[5];
    const float* hw = (const float*)d_in[6];
    const float* hb = (const float*)d_in[7];
    float* out = (float*)d_out;

    static int smem_set = 0;
    if (!smem_set) {
        cudaFuncSetAttribute(gemm_mma, cudaFuncAttributeMaxDynamicSharedMemorySize,
                             SMEM_TOTAL);
        smem_set = 1;
    }

    __nv_bfloat16 *xhi, *xlo, *fwh, *fwl, *iwh, *iwl, *hwh, *hwl;
    cudaGetSymbolAddress((void**)&xhi, g_xhi);
    cudaGetSymbolAddress((void**)&xlo, g_xlo);
    cudaGetSymbolAddress((void**)&fwh, g_fwhi);
    cudaGetSymbolAddress((void**)&fwl, g_fwlo);
    cudaGetSymbolAddress((void**)&iwh, g_iwhi);
    cudaGetSymbolAddress((void**)&iwl, g_iwlo);
    cudaGetSymbolAddress((void**)&hwh, g_hwhi);
    cudaGetSymbolAddress((void**)&hwl, g_hwlo);

    const int n4x = (Mn * Dn) / 4;
    const int n4w = (Hn * Dn) / 4;
    convert_split<<<(n4x + 255) / 256, 256>>>(x,  xhi, xlo, n4x);
    convert_split<<<(n4w + 255) / 256, 256>>>(fw, fwh, fwl, n4w);
    convert_split<<<(n4w + 255) / 256, 256>>>(iw, iwh, iwl, n4w);
    convert_split<<<(n4w + 255) / 256, 256>>>(hw, hwh, hwl, n4w);

    dim3 gGemm(Hn / TN, Mn / TM);   // (12, 256): N fastest -> weights L2-hot
    gemm_mma<<<gGemm, 256, SMEM_TOTAL>>>(fb, ib, hb);

    dim3 gScan((BHn / 4) / 256, NCH);
    scan_chunk<<<gScan, 256>>>();
    scan_carry<<<BHn / 256, 256>>>(h0);
    scan_apply<<<gScan, 256>>>(out);
}

// round 7
// speedup vs baseline: 1.2856x; 1.2856x over previous
#include <cuda_runtime.h>
#include <cuda_fp16.h>
#include <math.h>
#include <stdint.h>

// ---------------------------------------------------------------------------
// Problem constants (B=8, T=4096, D=H=768)
// ---------------------------------------------------------------------------
#define Bn   8
#define Tn   4096
#define Dn   768
#define Hn   768
#define Mn   (Bn * Tn)      // 32768
#define BHn  (Bn * Hn)      // 6144 scan lanes
#define NCH  64
#define TC   (Tn / NCH)     // 64

// GEMM tiling
#define TM   128            // CTA M tile
#define TN   64             // CTA N tile
#define BK   32             // K chunk per stage
#define NKI  (Dn / BK)      // 24 iterations

// Padded smem row: 32 halves data + 8 pad = 40 halves = 80 bytes.
// 8-row ldmatrix phases at stride 80B hit banks (r*20)%32 -> all distinct.
#define ROWB 80
#define A_TILE_B   (TM * ROWB)                     // 10240
#define B_TILE_B   (TN * ROWB)                     // 5120
#define STG_B      (2 * A_TILE_B + 3 * B_TILE_B)   // 35840
#define SMEM_TOTAL (2 * STG_B)                     // 71680

// ---------------------------------------------------------------------------
// Device scratch
// ---------------------------------------------------------------------------
__device__ float g_a [(size_t)Mn * Hn];
__device__ float g_bv[(size_t)Mn * Hn];
__device__ float g_cA [NCH * BHn];
__device__ float g_cB [NCH * BHn];
__device__ float g_hin[NCH * BHn];

__device__ __half g_xhi[(size_t)Mn * Dn];
__device__ __half g_xlo[(size_t)Mn * Dn];
__device__ __half g_fwh[Hn * Dn];
__device__ __half g_iwh[Hn * Dn];
__device__ __half g_hwh[Hn * Dn];

// ---------------------------------------------------------------------------
// Helpers
// ---------------------------------------------------------------------------
__device__ __forceinline__ uint32_t smem_u32(const void* p) {
    uint32_t a;
    asm("{ .reg .u64 t; cvta.to.shared.u64 t, %1; cvt.u32.u64 %0, t; }" : "=r"(a) : "l"(p));
    return a;
}
__device__ __forceinline__ void cpa16(uint32_t dst, const void* src) {
    asm volatile("cp.async.cg.shared.global [%0], [%1], 16;" :: "r"(dst), "l"(src) : "memory");
}
#define CPA_COMMIT() asm volatile("cp.async.commit_group;" ::: "memory")
#define CPA_WAIT1()  asm volatile("cp.async.wait_group 1;" ::: "memory")
#define CPA_WAIT0()  asm volatile("cp.async.wait_group 0;" ::: "memory")

__device__ __forceinline__ void ldm4(uint32_t& r0, uint32_t& r1,
                                     uint32_t& r2, uint32_t& r3, uint32_t a) {
    asm volatile("ldmatrix.sync.aligned.m8n8.x4.shared.b16 {%0,%1,%2,%3}, [%4];"
                 : "=r"(r0), "=r"(r1), "=r"(r2), "=r"(r3) : "r"(a));
}

// mma.sync m16n8k16 fp16 * fp16 -> f32, row.col
__device__ __forceinline__ void mma16816(float* c, const uint32_t* a, const uint32_t* b) {
    asm volatile(
        "mma.sync.aligned.m16n8k16.row.col.f32.f16.f16.f32 "
        "{%0,%1,%2,%3}, {%4,%5,%6,%7}, {%8,%9}, {%0,%1,%2,%3};"
        : "+f"(c[0]), "+f"(c[1]), "+f"(c[2]), "+f"(c[3])
        : "r"(a[0]), "r"(a[1]), "r"(a[2]), "r"(a[3]), "r"(b[0]), "r"(b[1]));
}

// ---------------------------------------------------------------------------
// Split-conversion: fp32 -> (fp16 hi, fp16 lo = fp16(v - hi))
// ---------------------------------------------------------------------------
__global__ void convert_split(const float* __restrict__ in,
                              __half* __restrict__ hi,
                              __half* __restrict__ lo, int n4) {
    int i = blockIdx.x * blockDim.x + threadIdx.x;
    if (i >= n4) return;
    float4 v = ((const float4*)in)[i];
    float f[4] = {v.x, v.y, v.z, v.w};
    __half h[4], l[4];
    #pragma unroll
    for (int q = 0; q < 4; q++) {
        h[q] = __float2half_rn(f[q]);
        l[q] = __float2half_rn(f[q] - __half2float(h[q]));
    }
    ((__half2*)hi)[2 * i]     = __halves2half2(h[0], h[1]);
    ((__half2*)hi)[2 * i + 1] = __halves2half2(h[2], h[3]);
    ((__half2*)lo)[2 * i]     = __halves2half2(l[0], l[1]);
    ((__half2*)lo)[2 * i + 1] = __halves2half2(l[2], l[3]);
}

// Single-round conversion for weights: fp32 -> fp16
__global__ void convert_one(const float* __restrict__ in,
                            __half* __restrict__ out, int n4) {
    int i = blockIdx.x * blockDim.x + threadIdx.x;
    if (i >= n4) return;
    float4 v = ((const float4*)in)[i];
    ((__half2*)out)[2 * i]     = __halves2half2(__float2half_rn(v.x), __float2half_rn(v.y));
    ((__half2*)out)[2 * i + 1] = __halves2half2(__float2half_rn(v.z), __float2half_rn(v.w));
}

// ---------------------------------------------------------------------------
// Triple-GEMM: x split (fp16 hi+lo) x single-fp16 weights = 2 MMA terms.
// Grid: x = H tiles (fast -> weights L2-hot), y = M tiles. Block 256 (8 warps).
// ---------------------------------------------------------------------------
__global__ __launch_bounds__(256, 1) void gemm_mma(
    const float* __restrict__ fb, const float* __restrict__ ib,
    const float* __restrict__ hb)
{
    extern __shared__ __align__(128) char smem[];
    const uint32_t sb = smem_u32(smem);
    const int tid = threadIdx.x;
    const int wid = tid >> 5;
    const int lid = tid & 31;
    const int g   = lid >> 2;
    const int tig = lid & 3;
    const int wm  = wid & 3;       // warp M index -> rows wm*32
    const int wn  = wid >> 2;      // warp N index -> cols wn*32
    const int bn  = blockIdx.x * TN;
    const int bm  = blockIdx.y * TM;

    // ldmatrix lane->address offsets
    const uint32_t aOff = (uint32_t)((lid & 15) * ROWB + (lid >> 4) * 16);
    const uint32_t bOff = (uint32_t)(((lid >> 4) * 8 + (lid & 7)) * ROWB
                                     + ((lid >> 3) & 1) * 16);

    // ---- stage loader (cp.async) ----
    auto issue_stage = [&](int stage, int k0) {
        const uint32_t s = sb + stage * STG_B;
        // A hi/lo: 128 rows x 4 chunks = 512 chunks each -> 2/thread
        #pragma unroll
        for (int rr = 0; rr < 2; rr++) {
            int i = tid + rr * 256;
            int row = i >> 2, c = i & 3;
            uint32_t dst = s + row * ROWB + c * 16;
            size_t gi = (size_t)(bm + row) * Dn + k0 + c * 8;
            cpa16(dst,            g_xhi + gi);
            cpa16(dst + A_TILE_B, g_xlo + gi);
        }
        // B tiles: 3 x (64 rows x 4 chunks = 256) -> 1/thread/tile
        {
            int row = tid >> 2, c = tid & 3;
            uint32_t dstb = s + 2 * A_TILE_B + row * ROWB + c * 16;
            size_t gi = (size_t)(bn + row) * Dn + k0 + c * 8;
            cpa16(dstb + 0 * B_TILE_B, g_fwh + gi);
            cpa16(dstb + 1 * B_TILE_B, g_iwh + gi);
            cpa16(dstb + 2 * B_TILE_B, g_hwh + gi);
        }
    };

    float acc[3][2][4][4];
    #pragma unroll
    for (int p = 0; p < 3; p++)
        #pragma unroll
        for (int mi = 0; mi < 2; mi++)
            #pragma unroll
            for (int ni = 0; ni < 4; ni++)
                #pragma unroll
                for (int q = 0; q < 4; q++) acc[p][mi][ni][q] = 0.0f;

    issue_stage(0, 0);  CPA_COMMIT();
    issue_stage(1, BK); CPA_COMMIT();

    for (int k = 0; k < NKI; k++) {
        if (k < NKI - 2) CPA_WAIT1(); else CPA_WAIT0();
        __syncthreads();

        const uint32_t s = sb + (k & 1) * STG_B;
        #pragma unroll
        for (int ks = 0; ks < 2; ks++) {
            const uint32_t kOff = ks * 32;

            uint32_t ah[2][4], al[2][4];
            const uint32_t aBase = s + (wm * 32) * ROWB + kOff + aOff;
            ldm4(ah[0][0], ah[0][1], ah[0][2], ah[0][3], aBase);
            ldm4(ah[1][0], ah[1][1], ah[1][2], ah[1][3], aBase + 16 * ROWB);
            ldm4(al[0][0], al[0][1], al[0][2], al[0][3], aBase + A_TILE_B);
            ldm4(al[1][0], al[1][1], al[1][2], al[1][3], aBase + A_TILE_B + 16 * ROWB);

            const uint32_t bBase = s + 2 * A_TILE_B + (wn * 32) * ROWB + kOff + bOff;
            #pragma unroll
            for (int p = 0; p < 3; p++) {
                uint32_t bw[4][2];
                const uint32_t ph = bBase + p * B_TILE_B;
                ldm4(bw[0][0], bw[0][1], bw[1][0], bw[1][1], ph);
                ldm4(bw[2][0], bw[2][1], bw[3][0], bw[3][1], ph + 16 * ROWB);
                #pragma unroll
                for (int mi = 0; mi < 2; mi++)
                    #pragma unroll
                    for (int ni = 0; ni < 4; ni++) {
                        mma16816(acc[p][mi][ni], ah[mi], bw[ni]);  // hi * w
                        mma16816(acc[p][mi][ni], al[mi], bw[ni]);  // lo * w
                    }
            }
        }
        __syncthreads();
        if (k + 2 < NKI) { issue_stage(k & 1, (k + 2) * BK); CPA_COMMIT(); }
    }

    // ---- epilogue: sigmoid gating -> g_a / g_bv ----
    #pragma unroll
    for (int ni = 0; ni < 4; ni++) {
        const int col = bn + wn * 32 + ni * 8 + tig * 2;
        const float fb0 = fb[col], fb1 = fb[col + 1];
        const float ib0 = ib[col], ib1 = ib[col + 1];
        const float hb0 = hb[col], hb1 = hb[col + 1];
        #pragma unroll
        for (int mi = 0; mi < 2; mi++) {
            #pragma unroll
            for (int half = 0; half < 2; half++) {
                const int m = bm + wm * 32 + mi * 16 + g + half * 8;
                const float F0 = acc[0][mi][ni][half * 2 + 0] + fb0;
                const float F1 = acc[0][mi][ni][half * 2 + 1] + fb1;
                const float I0 = acc[1][mi][ni][half * 2 + 0] + ib0;
                const float I1 = acc[1][mi][ni][half * 2 + 1] + ib1;
                const float H0 = acc[2][mi][ni][half * 2 + 0] + hb0;
                const float H1 = acc[2][mi][ni][half * 2 + 1] + hb1;
                const float f0 = 1.0f / (1.0f + expf(-F0));
                const float f1 = 1.0f / (1.0f + expf(-F1));
                const float i0 = 1.0f / (1.0f + expf(-I0));
                const float i1 = 1.0f / (1.0f + expf(-I1));
                const float v0 = 1.0f / (f0 + i0 + 1e-8f);
                const float v1 = 1.0f / (f1 + i1 + 1e-8f);
                float2 av = make_float2(f0 * v0, f1 * v1);
                float2 bv = make_float2(i0 * v0 * H0, i1 * v1 * H1);
                const size_t base = (size_t)m * Hn + col;
                *(float2*)&g_a [base] = av;
                *(float2*)&g_bv[base] = bv;
            }
        }
    }
}

// ---------------------------------------------------------------------------
// Scan (3-pass chunked), float4-vectorized over h.
// ---------------------------------------------------------------------------
__global__ __launch_bounds__(256) void scan_chunk()
{
    const int lane4 = blockIdx.x * blockDim.x + threadIdx.x;
    const int chunk = blockIdx.y;
    const int h4 = lane4 * 4;
    const int b = h4 / Hn;
    const int h = h4 - b * Hn;

    size_t idx = ((size_t)(b * Tn + chunk * TC)) * Hn + h;
    float4 A = make_float4(1.f, 1.f, 1.f, 1.f);
    float4 Bc = make_float4(0.f, 0.f, 0.f, 0.f);
    #pragma unroll 4
    for (int t = 0; t < TC; t++) {
        float4 a  = *(const float4*)&g_a [idx];
        float4 bb = *(const float4*)&g_bv[idx];
        Bc.x = fmaf(a.x, Bc.x, bb.x); A.x *= a.x;
        Bc.y = fmaf(a.y, Bc.y, bb.y); A.y *= a.y;
        Bc.z = fmaf(a.z, Bc.z, bb.z); A.z *= a.z;
        Bc.w = fmaf(a.w, Bc.w, bb.w); A.w *= a.w;
        idx += Hn;
    }
    *(float4*)&g_cA[chunk * BHn + h4] = A;
    *(float4*)&g_cB[chunk * BHn + h4] = Bc;
}

__global__ __launch_bounds__(256) void scan_carry(const float* __restrict__ h0)
{
    const int lane = blockIdx.x * blockDim.x + threadIdx.x;
    float h = h0[lane];
    #pragma unroll
    for (int c = 0; c < NCH; c++) {
        g_hin[c * BHn + lane] = h;
        h = fmaf(g_cA[c * BHn + lane], h, g_cB[c * BHn + lane]);
    }
}

__global__ __launch_bounds__(256) void scan_apply(float* __restrict__ out)
{
    const int lane4 = blockIdx.x * blockDim.x + threadIdx.x;
    const int chunk = blockIdx.y;
    const int h4 = lane4 * 4;
    const int b = h4 / Hn;
    const int h = h4 - b * Hn;

    float4 hc = *(const float4*)&g_hin[chunk * BHn + h4];
    size_t idx = ((size_t)(b * Tn + chunk * TC)) * Hn + h;
    #pragma unroll 4
    for (int t = 0; t < TC; t++) {
        float4 a  = *(const float4*)&g_a [idx];
        float4 bb = *(const float4*)&g_bv[idx];
        hc.x = fmaf(a.x, hc.x, bb.x);
        hc.y = fmaf(a.y, hc.y, bb.y);
        hc.z = fmaf(a.z, hc.z, bb.z);
        hc.w = fmaf(a.w, hc.w, bb.w);
        *(float4*)&out[idx] = hc;
        idx += Hn;
    }
}

// ---------------------------------------------------------------------------
// Launch
// ---------------------------------------------------------------------------
extern "C" void kernel_launch(void* const* d_in, const int* in_sizes, int n_in,
                              void* d_out, int out_size)
{
    const float* x  = (const float*)d_in[0];
    const float* h0 = (const float*)d_in[1];
    const float* fw = (const float*)d_in[2];
    const float* fb = (const float*)d_in[3];
    const float* iw = (const float*)d_in[4];
    const float* ib = (const float*)d_in[5];
    const float* hw = (const float*)d_in[6];
    const float* hb = (const float*)d_in[7];
    float* out = (float*)d_out;

    static int smem_set = 0;
    if (!smem_set) {
        cudaFuncSetAttribute(gemm_mma, cudaFuncAttributeMaxDynamicSharedMemorySize,
                             SMEM_TOTAL);
        smem_set = 1;
    }

    __half *xhi, *xlo, *fwh, *iwh, *hwh;
    cudaGetSymbolAddress((void**)&xhi, g_xhi);
    cudaGetSymbolAddress((void**)&xlo, g_xlo);
    cudaGetSymbolAddress((void**)&fwh, g_fwh);
    cudaGetSymbolAddress((void**)&iwh, g_iwh);
    cudaGetSymbolAddress((void**)&hwh, g_hwh);

    const int n4x = (Mn * Dn) / 4;
    const int n4w = (Hn * Dn) / 4;
    convert_split<<<(n4x + 255) / 256, 256>>>(x, xhi, xlo, n4x);
    convert_one<<<(n4w + 255) / 256, 256>>>(fw, fwh, n4w);
    convert_one<<<(n4w + 255) / 256, 256>>>(iw, iwh, n4w);
    convert_one<<<(n4w + 255) / 256, 256>>>(hw, hwh, n4w);

    dim3 gGemm(Hn / TN, Mn / TM);   // (12, 256): N fastest -> weights L2-hot
    gemm_mma<<<gGemm, 256, SMEM_TOTAL>>>(fb, ib, hb);

    dim3 gScan((BHn / 4) / 256, NCH);
    scan_chunk<<<gScan, 256>>>();
    scan_carry<<<BHn / 256, 256>>>(h0);
    scan_apply<<<gScan, 256>>>(out);
}

// round 8
// speedup vs baseline: 1.7630x; 1.3713x over previous
#include <cuda_runtime.h>
#include <cuda_fp16.h>
#include <math.h>
#include <stdint.h>

// ---------------------------------------------------------------------------
// Problem constants (B=8, T=4096, D=H=768)
// ---------------------------------------------------------------------------
#define Bn   8
#define Tn   4096
#define Dn   768
#define Hn   768
#define Mn   (Bn * Tn)      // 32768
#define BHn  (Bn * Hn)      // 6144 scan lanes
#define NCH  64
#define TC   (Tn / NCH)     // 64

// GEMM tiling
#define TM   128            // CTA M tile
#define TN   64             // CTA N tile
#define BK   32             // K chunk per stage
#define NKI  (Dn / BK)      // 24 iterations

// Padded smem row: 32 halves data + 8 pad = 40 halves = 80 bytes.
// 8-row ldmatrix phases at stride 80B hit banks (r*20)%32 -> all distinct.
#define ROWB 80
#define A_TILE_B   (TM * ROWB)                     // 10240
#define B_TILE_B   (TN * ROWB)                     // 5120
#define STG_B      (A_TILE_B + 3 * B_TILE_B)       // 25600
#define SMEM_TOTAL (2 * STG_B)                     // 51200

// ---------------------------------------------------------------------------
// Device scratch
// ---------------------------------------------------------------------------
__device__ float g_a [(size_t)Mn * Hn];
__device__ float g_bv[(size_t)Mn * Hn];
__device__ float g_cA [NCH * BHn];
__device__ float g_cB [NCH * BHn];
__device__ float g_hin[NCH * BHn];

__device__ __half g_xh [(size_t)Mn * Dn];
__device__ __half g_fwh[Hn * Dn];
__device__ __half g_iwh[Hn * Dn];
__device__ __half g_hwh[Hn * Dn];

// ---------------------------------------------------------------------------
// Helpers
// ---------------------------------------------------------------------------
__device__ __forceinline__ uint32_t smem_u32(const void* p) {
    uint32_t a;
    asm("{ .reg .u64 t; cvta.to.shared.u64 t, %1; cvt.u32.u64 %0, t; }" : "=r"(a) : "l"(p));
    return a;
}
__device__ __forceinline__ void cpa16(uint32_t dst, const void* src) {
    asm volatile("cp.async.cg.shared.global [%0], [%1], 16;" :: "r"(dst), "l"(src) : "memory");
}
#define CPA_COMMIT() asm volatile("cp.async.commit_group;" ::: "memory")
#define CPA_WAIT1()  asm volatile("cp.async.wait_group 1;" ::: "memory")
#define CPA_WAIT0()  asm volatile("cp.async.wait_group 0;" ::: "memory")

__device__ __forceinline__ void ldm4(uint32_t& r0, uint32_t& r1,
                                     uint32_t& r2, uint32_t& r3, uint32_t a) {
    asm volatile("ldmatrix.sync.aligned.m8n8.x4.shared.b16 {%0,%1,%2,%3}, [%4];"
                 : "=r"(r0), "=r"(r1), "=r"(r2), "=r"(r3) : "r"(a));
}

// mma.sync m16n8k16 fp16 * fp16 -> f32, row.col
__device__ __forceinline__ void mma16816(float* c, const uint32_t* a, const uint32_t* b) {
    asm volatile(
        "mma.sync.aligned.m16n8k16.row.col.f32.f16.f16.f32 "
        "{%0,%1,%2,%3}, {%4,%5,%6,%7}, {%8,%9}, {%0,%1,%2,%3};"
        : "+f"(c[0]), "+f"(c[1]), "+f"(c[2]), "+f"(c[3])
        : "r"(a[0]), "r"(a[1]), "r"(a[2]), "r"(a[3]), "r"(b[0]), "r"(b[1]));
}

// ---------------------------------------------------------------------------
// Conversion: fp32 -> fp16 (single rounding)
// ---------------------------------------------------------------------------
__global__ void convert_one(const float* __restrict__ in,
                            __half* __restrict__ out, int n4) {
    int i = blockIdx.x * blockDim.x + threadIdx.x;
    if (i >= n4) return;
    float4 v = ((const float4*)in)[i];
    ((__half2*)out)[2 * i]     = __halves2half2(__float2half_rn(v.x), __float2half_rn(v.y));
    ((__half2*)out)[2 * i + 1] = __halves2half2(__float2half_rn(v.z), __float2half_rn(v.w));
}

// ---------------------------------------------------------------------------
// Triple-GEMM: single fp16 term per projection + fused gating epilogue.
// Grid: x = H tiles (fast -> weights L2-hot), y = M tiles. Block 256 (8 warps).
// ---------------------------------------------------------------------------
__global__ __launch_bounds__(256, 1) void gemm_mma(
    const float* __restrict__ fb, const float* __restrict__ ib,
    const float* __restrict__ hb)
{
    extern __shared__ __align__(128) char smem[];
    const uint32_t sb = smem_u32(smem);
    const int tid = threadIdx.x;
    const int wid = tid >> 5;
    const int lid = tid & 31;
    const int g   = lid >> 2;
    const int tig = lid & 3;
    const int wm  = wid & 3;       // warp M index -> rows wm*32
    const int wn  = wid >> 2;      // warp N index -> cols wn*32
    const int bn  = blockIdx.x * TN;
    const int bm  = blockIdx.y * TM;

    // ldmatrix lane->address offsets
    const uint32_t aOff = (uint32_t)((lid & 15) * ROWB + (lid >> 4) * 16);
    const uint32_t bOff = (uint32_t)(((lid >> 4) * 8 + (lid & 7)) * ROWB
                                     + ((lid >> 3) & 1) * 16);

    // ---- stage loader (cp.async): A 512 chunks (2/thread) + 3B (1/thread ea)
    auto issue_stage = [&](int stage, int k0) {
        const uint32_t s = sb + stage * STG_B;
        #pragma unroll
        for (int rr = 0; rr < 2; rr++) {
            int i = tid + rr * 256;
            int row = i >> 2, c = i & 3;
            uint32_t dst = s + row * ROWB + c * 16;
            size_t gi = (size_t)(bm + row) * Dn + k0 + c * 8;
            cpa16(dst, g_xh + gi);
        }
        {
            int row = tid >> 2, c = tid & 3;
            uint32_t dstb = s + A_TILE_B + row * ROWB + c * 16;
            size_t gi = (size_t)(bn + row) * Dn + k0 + c * 8;
            cpa16(dstb + 0 * B_TILE_B, g_fwh + gi);
            cpa16(dstb + 1 * B_TILE_B, g_iwh + gi);
            cpa16(dstb + 2 * B_TILE_B, g_hwh + gi);
        }
    };

    float acc[3][2][4][4];
    #pragma unroll
    for (int p = 0; p < 3; p++)
        #pragma unroll
        for (int mi = 0; mi < 2; mi++)
            #pragma unroll
            for (int ni = 0; ni < 4; ni++)
                #pragma unroll
                for (int q = 0; q < 4; q++) acc[p][mi][ni][q] = 0.0f;

    issue_stage(0, 0);  CPA_COMMIT();
    issue_stage(1, BK); CPA_COMMIT();

    for (int k = 0; k < NKI; k++) {
        if (k < NKI - 2) CPA_WAIT1(); else CPA_WAIT0();
        __syncthreads();

        const uint32_t s = sb + (k & 1) * STG_B;
        #pragma unroll
        for (int ks = 0; ks < 2; ks++) {
            const uint32_t kOff = ks * 32;

            uint32_t ah[2][4];
            const uint32_t aBase = s + (wm * 32) * ROWB + kOff + aOff;
            ldm4(ah[0][0], ah[0][1], ah[0][2], ah[0][3], aBase);
            ldm4(ah[1][0], ah[1][1], ah[1][2], ah[1][3], aBase + 16 * ROWB);

            const uint32_t bBase = s + A_TILE_B + (wn * 32) * ROWB + kOff + bOff;
            #pragma unroll
            for (int p = 0; p < 3; p++) {
                uint32_t bw[4][2];
                const uint32_t ph = bBase + p * B_TILE_B;
                ldm4(bw[0][0], bw[0][1], bw[1][0], bw[1][1], ph);
                ldm4(bw[2][0], bw[2][1], bw[3][0], bw[3][1], ph + 16 * ROWB);
                #pragma unroll
                for (int mi = 0; mi < 2; mi++)
                    #pragma unroll
                    for (int ni = 0; ni < 4; ni++)
                        mma16816(acc[p][mi][ni], ah[mi], bw[ni]);
            }
        }
        __syncthreads();
        if (k + 2 < NKI) { issue_stage(k & 1, (k + 2) * BK); CPA_COMMIT(); }
    }

    // ---- epilogue: sigmoid gating -> g_a / g_bv ----
    #pragma unroll
    for (int ni = 0; ni < 4; ni++) {
        const int col = bn + wn * 32 + ni * 8 + tig * 2;
        const float fb0 = fb[col], fb1 = fb[col + 1];
        const float ib0 = ib[col], ib1 = ib[col + 1];
        const float hb0 = hb[col], hb1 = hb[col + 1];
        #pragma unroll
        for (int mi = 0; mi < 2; mi++) {
            #pragma unroll
            for (int half = 0; half < 2; half++) {
                const int m = bm + wm * 32 + mi * 16 + g + half * 8;
                const float F0 = acc[0][mi][ni][half * 2 + 0] + fb0;
                const float F1 = acc[0][mi][ni][half * 2 + 1] + fb1;
                const float I0 = acc[1][mi][ni][half * 2 + 0] + ib0;
                const float I1 = acc[1][mi][ni][half * 2 + 1] + ib1;
                const float H0 = acc[2][mi][ni][half * 2 + 0] + hb0;
                const float H1 = acc[2][mi][ni][half * 2 + 1] + hb1;
                const float f0 = 1.0f / (1.0f + expf(-F0));
                const float f1 = 1.0f / (1.0f + expf(-F1));
                const float i0 = 1.0f / (1.0f + expf(-I0));
                const float i1 = 1.0f / (1.0f + expf(-I1));
                const float v0 = 1.0f / (f0 + i0 + 1e-8f);
                const float v1 = 1.0f / (f1 + i1 + 1e-8f);
                float2 av = make_float2(f0 * v0, f1 * v1);
                float2 bv = make_float2(i0 * v0 * H0, i1 * v1 * H1);
                const size_t base = (size_t)m * Hn + col;
                *(float2*)&g_a [base] = av;
                *(float2*)&g_bv[base] = bv;
            }
        }
    }
}

// ---------------------------------------------------------------------------
// Scan (3-pass chunked), float4-vectorized over h.
// ---------------------------------------------------------------------------
__global__ __launch_bounds__(256) void scan_chunk()
{
    const int lane4 = blockIdx.x * blockDim.x + threadIdx.x;
    const int chunk = blockIdx.y;
    const int h4 = lane4 * 4;
    const int b = h4 / Hn;
    const int h = h4 - b * Hn;

    size_t idx = ((size_t)(b * Tn + chunk * TC)) * Hn + h;
    float4 A = make_float4(1.f, 1.f, 1.f, 1.f);
    float4 Bc = make_float4(0.f, 0.f, 0.f, 0.f);
    #pragma unroll 4
    for (int t = 0; t < TC; t++) {
        float4 a  = *(const float4*)&g_a [idx];
        float4 bb = *(const float4*)&g_bv[idx];
        Bc.x = fmaf(a.x, Bc.x, bb.x); A.x *= a.x;
        Bc.y = fmaf(a.y, Bc.y, bb.y); A.y *= a.y;
        Bc.z = fmaf(a.z, Bc.z, bb.z); A.z *= a.z;
        Bc.w = fmaf(a.w, Bc.w, bb.w); A.w *= a.w;
        idx += Hn;
    }
    *(float4*)&g_cA[chunk * BHn + h4] = A;
    *(float4*)&g_cB[chunk * BHn + h4] = Bc;
}

__global__ __launch_bounds__(256) void scan_carry(const float* __restrict__ h0)
{
    const int lane = blockIdx.x * blockDim.x + threadIdx.x;
    float h = h0[lane];
    #pragma unroll
    for (int c = 0; c < NCH; c++) {
        g_hin[c * BHn + lane] = h;
        h = fmaf(g_cA[c * BHn + lane], h, g_cB[c * BHn + lane]);
    }
}

__global__ __launch_bounds__(256) void scan_apply(float* __restrict__ out)
{
    const int lane4 = blockIdx.x * blockDim.x + threadIdx.x;
    const int chunk = blockIdx.y;
    const int h4 = lane4 * 4;
    const int b = h4 / Hn;
    const int h = h4 - b * Hn;

    float4 hc = *(const float4*)&g_hin[chunk * BHn + h4];
    size_t idx = ((size_t)(b * Tn + chunk * TC)) * Hn + h;
    #pragma unroll 4
    for (int t = 0; t < TC; t++) {
        float4 a  = *(const float4*)&g_a [idx];
        float4 bb = *(const float4*)&g_bv[idx];
        hc.x = fmaf(a.x, hc.x, bb.x);
        hc.y = fmaf(a.y, hc.y, bb.y);
        hc.z = fmaf(a.z, hc.z, bb.z);
        hc.w = fmaf(a.w, hc.w, bb.w);
        *(float4*)&out[idx] = hc;
        idx += Hn;
    }
}

// ---------------------------------------------------------------------------
// Launch
// ---------------------------------------------------------------------------
extern "C" void kernel_launch(void* const* d_in, const int* in_sizes, int n_in,
                              void* d_out, int out_size)
{
    const float* x  = (const float*)d_in[0];
    const float* h0 = (const float*)d_in[1];
    const float* fw = (const float*)d_in[2];
    const float* fb = (const float*)d_in[3];
    const float* iw = (const float*)d_in[4];
    const float* ib = (const float*)d_in[5];
    const float* hw = (const float*)d_in[6];
    const float* hb = (const float*)d_in[7];
    float* out = (float*)d_out;

    static int smem_set = 0;
    if (!smem_set) {
        cudaFuncSetAttribute(gemm_mma, cudaFuncAttributeMaxDynamicSharedMemorySize,
                             SMEM_TOTAL);
        smem_set = 1;
    }

    __half *xh, *fwh, *iwh, *hwh;
    cudaGetSymbolAddress((void**)&xh,  g_xh);
    cudaGetSymbolAddress((void**)&fwh, g_fwh);
    cudaGetSymbolAddress((void**)&iwh, g_iwh);
    cudaGetSymbolAddress((void**)&hwh, g_hwh);

    const int n4x = (Mn * Dn) / 4;
    const int n4w = (Hn * Dn) / 4;
    convert_one<<<(n4x + 255) / 256, 256>>>(x, xh, n4x);
    convert_one<<<(n4w + 255) / 256, 256>>>(fw, fwh, n4w);
    convert_one<<<(n4w + 255) / 256, 256>>>(iw, iwh, n4w);
    convert_one<<<(n4w + 255) / 256, 256>>>(hw, hwh, n4w);

    dim3 gGemm(Hn / TN, Mn / TM);   // (12, 256): N fastest -> weights L2-hot
    gemm_mma<<<gGemm, 256, SMEM_TOTAL>>>(fb, ib, hb);

    dim3 gScan((BHn / 4) / 256, NCH);
    scan_chunk<<<gScan, 256>>>();
    scan_carry<<<BHn / 256, 256>>>(h0);
    scan_apply<<<gScan, 256>>>(out);
}